// round 13
// baseline (speedup 1.0000x reference)
#include <cuda_runtime.h>
#include <cuda.h>
#include <cuda_bf16.h>
#include <cstdint>
#include <cstddef>
#include <cstring>

// ============================================================================
// out[M,N] = ((x + 66)*0.03) @ ((y - 160)*0.025)
// (x+66), (y-160) are exact integers in bf16 -> bf16 HMMA GEMM (fp32 acc),
// scale 7.5e-4 in epilogue.
// R13: GEMM reverted byte-for-byte to R11 (best: 338.7us — TK=64, 4-stage
// cp.async ring, 64x64 warp tile, bulk per-k16 fragment double-buffering,
// wave-quantization tile split). R12's 2-stage/TK128 ring regressed (slack
// loss) and is abandoned. New: x-convert and yT-convert fused into ONE
// kernel (disjoint grid halves) so both DRAM streams run concurrently.
// ============================================================================

static constexpr int MDIM = 4096, NDIM = 4096, KDIM = 4096;

static constexpr int TM = 128;        // CTA M tile
static constexpr int TKE = 64;        // K elems (bf16) per stage = 128 B rows
static constexpr int NK = KDIM / TKE; // 64 mainloop iters
static constexpr int STAGES = 4;
static constexpr int NTHREADS = 256;  // 8 warps: 2 (m) x 4 (n)
static constexpr int A_STG = TM * 128;              // 16 KB
static constexpr int SMEM_TOTAL = STAGES * (A_STG + 256 * 128);  // 192 KB

static constexpr int NTILE = (MDIM / 128) * (NDIM / 256);   // 512 logical tiles

static constexpr float OUT_SCALE = 0.03f * 0.025f;   // 7.5e-4

// Scratch operands (device globals: no runtime allocation allowed)
__device__ __nv_bfloat16 g_xb[(size_t)MDIM * KDIM];   // A [M,K]: bf16(x+66)
__device__ __nv_bfloat16 g_yb[(size_t)NDIM * KDIM];   // Bt [N,K]: bf16(y-160)

#define DEVINL __device__ __forceinline__

DEVINL uint32_t smem_u32(const void* p) {
    uint32_t a;
    asm("{ .reg .u64 t; cvta.to.shared.u64 t, %1; cvt.u32.u64 %0, t; }"
        : "=r"(a) : "l"(p));
    return a;
}

DEVINL void cp_async16(uint32_t dst, const void* src) {
    asm volatile("cp.async.cg.shared.global [%0], [%1], 16;"
                 :: "r"(dst), "l"(src) : "memory");
}
DEVINL void cp_commit() { asm volatile("cp.async.commit_group;" ::: "memory"); }
template <int N>
DEVINL void cp_wait() { asm volatile("cp.async.wait_group %0;" :: "n"(N) : "memory"); }

DEVINL void ldsm4(uint32_t* r, uint32_t addr) {
    asm volatile("ldmatrix.sync.aligned.m8n8.x4.shared.b16 {%0,%1,%2,%3}, [%4];"
                 : "=r"(r[0]), "=r"(r[1]), "=r"(r[2]), "=r"(r[3]) : "r"(addr));
}

// m16n8k16 bf16 HMMA, f32 accumulate
DEVINL void mma_bf16(float* c, const uint32_t* a, const uint32_t* b) {
    asm volatile(
        "mma.sync.aligned.m16n8k16.row.col.f32.bf16.bf16.f32 "
        "{%0,%1,%2,%3}, {%4,%5,%6,%7}, {%8,%9}, {%0,%1,%2,%3};"
        : "+f"(c[0]), "+f"(c[1]), "+f"(c[2]), "+f"(c[3])
        : "r"(a[0]), "r"(a[1]), "r"(a[2]), "r"(a[3]), "r"(b[0]), "r"(b[1]));
}

// ============================================================================
// Fused conversion kernel (exact: shifted values are integers, |v| <= 256).
// Blocks [0, XBLKS): x int32 [M,K] -> bf16 (x+66), 32B load / 16B store.
// Blocks [XBLKS, XBLKS+YBLKS): y int32 [K,N] -> bf16 yT [N,K] (y-160),
// 64(K) x 32(N) transpose tiles via padded smem.
// ============================================================================
static constexpr int XBLKS = (MDIM * KDIM / 8) / 256;            // 8192
static constexpr int YBLKS = (NDIM / 32) * (KDIM / 64);          // 8192

DEVINL uint32_t pack_bf2(float a, float b) {
    __nv_bfloat162 p = __floats2bfloat162_rn(a, b);
    uint32_t u;
    memcpy(&u, &p, 4);
    return u;
}

__global__ void __launch_bounds__(256)
convert_fused_kernel(const int4* __restrict__ x4, const int* __restrict__ y,
                     uint4* __restrict__ xb4, __nv_bfloat16* __restrict__ yT) {
    __shared__ __nv_bfloat16 tile[64][33];   // [k][n], padded (yT half only)
    int bid = blockIdx.x;
    int tid = threadIdx.x;

    if (bid < XBLKS) {
        // ---- x part: 8 int32 -> 8 bf16 per thread ----
        int i = bid * 256 + tid;
        int4 v0 = x4[2 * i];
        int4 v1 = x4[2 * i + 1];
        uint4 o;
        o.x = pack_bf2((float)(v0.x + 66), (float)(v0.y + 66));
        o.y = pack_bf2((float)(v0.z + 66), (float)(v0.w + 66));
        o.z = pack_bf2((float)(v1.x + 66), (float)(v1.y + 66));
        o.w = pack_bf2((float)(v1.z + 66), (float)(v1.w + 66));
        xb4[i] = o;
    } else {
        // ---- yT part: 64(K) x 32(N) transpose tile ----
        int b = bid - XBLKS;
        int n0 = (b & 127) * 32;          // 128 n-tiles
        int k0 = (b >> 7) * 64;           // 64 k-tiles
        int tx = tid & 31;                // 0..31 (n)
        int ty = tid >> 5;                // 0..7

#pragma unroll
        for (int kk = ty; kk < 64; kk += 8) {
            int vv = y[(size_t)(k0 + kk) * NDIM + n0 + tx] - 160;
            tile[kk][tx] = __float2bfloat16_rn((float)vv);
        }
        __syncthreads();
#pragma unroll
        for (int nn = ty; nn < 32; nn += 8) {
            __nv_bfloat162 p;
            p.x = tile[2 * tx + 0][nn];
            p.y = tile[2 * tx + 1][nn];
            *(__nv_bfloat162*)(&yT[(size_t)(n0 + nn) * KDIM + k0 + 2 * tx]) = p;
        }
    }
}

// ============================================================================
// GEMM tile body (R11). 8 warps = 2(m) x 4(n); warp tile 64 x (16*TNN).
// TNN=4: CTA 128x256 (acc 128 regs). TNN=2: CTA 128x128 (tail).
// mma.m16n8k16.bf16, 4-stage cp.async ring, XOR-swizzled smem,
// bulk per-k16-step register double-buffered fragments.
// ============================================================================
template <int TNN>
DEVINL void gemm_tile(float* __restrict__ out, uint32_t sb, int tid,
                      int m0, int n0) {
    const char* A = (const char*)g_xb;
    const char* B = (const char*)g_yb;

    constexpr int TN = 64 * TNN;                  // 256 / 128
    constexpr int B_STG = TN * 128;               // 32 KB / 16 KB
    constexpr int STG_BYTES = A_STG + B_STG;      // 48 KB / 32 KB

    const int lane = tid & 31;
    const int wid = tid >> 5;      // 0..7
    const int wm = wid & 1;        // m: 0..1
    const int wn = wid >> 1;       // n: 0..3

    const int frag_row = ((lane >> 3) & 1) * 8 + (lane & 7);
    const int frag_kh = lane >> 4;

    const int rowA0 = wm * 64 + frag_row;           // + tm*16, tm<4
    const int rowB0 = wn * (TNN * 16) + frag_row;   // + gg*16, gg<TNN

    float acc[TNN * 32];
#pragma unroll
    for (int i = 0; i < TNN * 32; ++i) acc[i] = 0.0f;

    auto stage_copy = [&](int slot, int kt) {
        uint32_t abase = sb + slot * STG_BYTES;
        uint32_t bbase = abase + A_STG;
#pragma unroll
        for (int i = 0; i < 4; ++i) {               // A: 1024 chunks / 256 thr
            int idx = tid + i * NTHREADS;
            int row = idx >> 3, c = idx & 7;
            cp_async16(abase + row * 128 + ((c ^ (row & 7)) << 4),
                       A + (size_t)(m0 + row) * (KDIM * 2) + kt * 128 + c * 16);
        }
#pragma unroll
        for (int i = 0; i < 2 * TNN; ++i) {         // B: TN*8 chunks / 256 thr
            int idx = tid + i * NTHREADS;
            int row = idx >> 3, c = idx & 7;
            cp_async16(bbase + row * 128 + ((c ^ (row & 7)) << 4),
                       B + (size_t)(n0 + row) * (KDIM * 2) + kt * 128 + c * 16);
        }
    };

    auto load_A = [&](uint32_t abase, int ks, uint32_t afr[4][4]) {
#pragma unroll
        for (int tm = 0; tm < 4; ++tm) {
            int rowa = rowA0 + tm * 16;
            ldsm4(afr[tm],
                  abase + rowa * 128 + (((ks * 2 + frag_kh) ^ (rowa & 7)) << 4));
        }
    };
    auto load_B = [&](uint32_t bbase, int ks, uint32_t bfr[2 * TNN][2]) {
#pragma unroll
        for (int gg = 0; gg < TNN; ++gg) {
            uint32_t t4[4];
            int rowb = rowB0 + gg * 16;
            ldsm4(t4,
                  bbase + rowb * 128 + (((ks * 2 + frag_kh) ^ (rowb & 7)) << 4));
            bfr[2 * gg][0] = t4[0]; bfr[2 * gg][1] = t4[2];
            bfr[2 * gg + 1][0] = t4[1]; bfr[2 * gg + 1][1] = t4[3];
        }
    };

    // prologue
#pragma unroll
    for (int s = 0; s < STAGES - 1; ++s) {
        stage_copy(s, s);
        cp_commit();
    }
    cp_wait<STAGES - 2>();
    __syncthreads();

    uint32_t afr[2][4][4];
    uint32_t bfr[2][2 * TNN][2];
    int cur = 0;
    load_A(sb, 0, afr[0]);
    load_B(sb + A_STG, 0, bfr[0]);

    for (int kt = 0; kt < NK; ++kt) {
        int pf = kt + STAGES - 1;
        if (pf < NK) stage_copy(pf & 3, pf);
        cp_commit();

        uint32_t abase = sb + (kt & 3) * STG_BYTES;
        uint32_t bbase = abase + A_STG;
        uint32_t abase_n = sb + ((kt + 1) & 3) * STG_BYTES;
        uint32_t bbase_n = abase_n + A_STG;

#pragma unroll
        for (int ks = 0; ks < 4; ++ks) {
            int nxt = cur ^ 1;
            if (ks < 3) {
                // prefetch (kt, ks+1) while mma on (kt, ks)
                load_A(abase, ks + 1, afr[nxt]);
                load_B(bbase, ks + 1, bfr[nxt]);
            } else {
                // stage kt+1 becomes resident; prefetch its ks0
                cp_wait<STAGES - 2>();
                __syncthreads();
                load_A(abase_n, 0, afr[nxt]);
                load_B(bbase_n, 0, bfr[nxt]);
            }
#pragma unroll
            for (int tm = 0; tm < 4; ++tm)
#pragma unroll
                for (int tn = 0; tn < 2 * TNN; ++tn)
                    mma_bf16(&acc[(tm * 2 * TNN + tn) * 4],
                             afr[cur][tm], bfr[cur][tn]);
            cur = nxt;
        }
    }

    // epilogue: scale + store
    const int gq = lane >> 2;
    const int tig = lane & 3;
#pragma unroll
    for (int tm = 0; tm < 4; ++tm) {
        int m_top = m0 + wm * 64 + tm * 16 + gq;
        float* row0 = out + (size_t)m_top * NDIM;
        float* row1 = out + (size_t)(m_top + 8) * NDIM;
#pragma unroll
        for (int tn = 0; tn < 2 * TNN; ++tn) {
            int n = n0 + wn * (TNN * 16) + tn * 8 + tig * 2;
            const float* c = &acc[(tm * 2 * TNN + tn) * 4];
            float2 v0, v1;
            v0.x = c[0] * OUT_SCALE;
            v0.y = c[1] * OUT_SCALE;
            v1.x = c[2] * OUT_SCALE;
            v1.y = c[3] * OUT_SCALE;
            *(float2*)(row0 + n) = v0;
            *(float2*)(row1 + n) = v1;
        }
    }
}

// Rasterization over the 512 logical 128x256 tiles: groups of 8 m-tiles,
// n fast within group.
DEVINL void tile_coords(int t, int& m0, int& n0) {
    int g = t >> 7;
    int r = t & 127;
    m0 = (g * 8 + (r & 7)) * 128;
    n0 = (r >> 3) * 256;
}

__global__ void __launch_bounds__(NTHREADS, 1)
gemm_kernel(float* __restrict__ out, int nbig) {
    extern __shared__ __align__(1024) char smem[];
    const uint32_t sb = smem_u32(smem);
    const int tid = threadIdx.x;
    const int pid = blockIdx.x;

    if (pid < nbig) {
        int m0, n0;
        tile_coords(pid, m0, n0);
        gemm_tile<4>(out, sb, tid, m0, n0);
    } else {
        int s = pid - nbig;
        int m0, n0;
        tile_coords(nbig + (s >> 1), m0, n0);
        n0 += (s & 1) * 128;
        gemm_tile<2>(out, sb, tid, m0, n0);
    }
}

// ============================================================================
// Host
// ============================================================================
extern "C" void kernel_launch(void* const* d_in, const int* in_sizes, int n_in,
                              void* d_out, int out_size) {
    const int* x = (const int*)d_in[0];   // [M,K] int32
    const int* y = (const int*)d_in[1];   // [K,N] int32
    float* out = (float*)d_out;

    void *pxb = nullptr, *pyb = nullptr;
    cudaGetSymbolAddress(&pxb, g_xb);
    cudaGetSymbolAddress(&pyb, g_yb);

    // 1) fused conversions: x and yT halves run concurrently
    convert_fused_kernel<<<XBLKS + YBLKS, 256>>>(
        (const int4*)x, y, (uint4*)pxb, (__nv_bfloat16*)pyb);

    // 2) GEMM
    static int sms = 0;
    static bool attr_set = false;
    if (!attr_set) {
        cudaFuncSetAttribute(gemm_kernel,
                             cudaFuncAttributeMaxDynamicSharedMemorySize,
                             SMEM_TOTAL);
        int dev = 0;
        cudaGetDevice(&dev);
        cudaDeviceGetAttribute(&sms, cudaDevAttrMultiProcessorCount, dev);
        if (sms <= 0) sms = 148;
        attr_set = true;
    }

    int w = NTILE / sms;                 // full big-tile waves
    int nbig = w * sms;
    if (nbig > NTILE) nbig = NTILE;
    int rem = NTILE - nbig;              // big-tile footprints left
    int grid = nbig + 2 * rem;           // each footprint -> two 128x128 CTAs

    gemm_kernel<<<grid, NTHREADS, SMEM_TOTAL>>>(out, nbig);
}

// round 14
// speedup vs baseline: 1.4196x; 1.4196x over previous
#include <cuda_runtime.h>
#include <cuda.h>
#include <cuda_bf16.h>
#include <cstdint>
#include <cstddef>
#include <cstring>

// ============================================================================
// out[M,N] = ((x + 66)*0.03) @ ((y - 160)*0.025)
// (x+66), (y-160) are exact integers in bf16 -> bf16 HMMA GEMM (fp32 acc),
// scale 7.5e-4 in epilogue.
// R14: exact revert to R11 (best: 338.7us). R13 (= R11 + fused converts)
// measured 480us but ncu arithmetic shows the SM clock was ~1.27 GHz vs
// ~1.9 GHz in R11 with byte-identical GEMM code -> environmental throttling,
// not a code effect. Reverting to the proven source to recover/confirm.
// Config: TK=64, 4-stage cp.async ring, 64x64 warp tile (8 warps, 256 thr),
// bulk per-k16 register double-buffered fragments, wave-quantization split.
// ============================================================================

static constexpr int MDIM = 4096, NDIM = 4096, KDIM = 4096;

static constexpr int TM = 128;        // CTA M tile
static constexpr int TKE = 64;        // K elems (bf16) per stage = 128 B rows
static constexpr int NK = KDIM / TKE; // 64 mainloop iters
static constexpr int STAGES = 4;
static constexpr int NTHREADS = 256;  // 8 warps: 2 (m) x 4 (n)
static constexpr int A_STG = TM * 128;              // 16 KB
static constexpr int SMEM_TOTAL = STAGES * (A_STG + 256 * 128);  // 192 KB

static constexpr int NTILE = (MDIM / 128) * (NDIM / 256);   // 512 logical tiles

static constexpr float OUT_SCALE = 0.03f * 0.025f;   // 7.5e-4

// Scratch operands (device globals: no runtime allocation allowed)
__device__ __nv_bfloat16 g_xb[(size_t)MDIM * KDIM];   // A [M,K]: bf16(x+66)
__device__ __nv_bfloat16 g_yb[(size_t)NDIM * KDIM];   // Bt [N,K]: bf16(y-160)

#define DEVINL __device__ __forceinline__

DEVINL uint32_t smem_u32(const void* p) {
    uint32_t a;
    asm("{ .reg .u64 t; cvta.to.shared.u64 t, %1; cvt.u32.u64 %0, t; }"
        : "=r"(a) : "l"(p));
    return a;
}

DEVINL void cp_async16(uint32_t dst, const void* src) {
    asm volatile("cp.async.cg.shared.global [%0], [%1], 16;"
                 :: "r"(dst), "l"(src) : "memory");
}
DEVINL void cp_commit() { asm volatile("cp.async.commit_group;" ::: "memory"); }
template <int N>
DEVINL void cp_wait() { asm volatile("cp.async.wait_group %0;" :: "n"(N) : "memory"); }

DEVINL void ldsm4(uint32_t* r, uint32_t addr) {
    asm volatile("ldmatrix.sync.aligned.m8n8.x4.shared.b16 {%0,%1,%2,%3}, [%4];"
                 : "=r"(r[0]), "=r"(r[1]), "=r"(r[2]), "=r"(r[3]) : "r"(addr));
}

// m16n8k16 bf16 HMMA, f32 accumulate
DEVINL void mma_bf16(float* c, const uint32_t* a, const uint32_t* b) {
    asm volatile(
        "mma.sync.aligned.m16n8k16.row.col.f32.bf16.bf16.f32 "
        "{%0,%1,%2,%3}, {%4,%5,%6,%7}, {%8,%9}, {%0,%1,%2,%3};"
        : "+f"(c[0]), "+f"(c[1]), "+f"(c[2]), "+f"(c[3])
        : "r"(a[0]), "r"(a[1]), "r"(a[2]), "r"(a[3]), "r"(b[0]), "r"(b[1]));
}

// ============================================================================
// Conversion kernels (exact: all shifted values are integers with |v| <= 256)
// ============================================================================

DEVINL uint32_t pack_bf2(float a, float b) {
    __nv_bfloat162 p = __floats2bfloat162_rn(a, b);
    uint32_t u;
    memcpy(&u, &p, 4);
    return u;
}

// x int32 [M,K] -> bf16 (x+66). 32B load / 16B store per thread.
__global__ void convert_x_kernel(const int4* __restrict__ in,
                                 uint4* __restrict__ out, int n8) {
    int i = blockIdx.x * blockDim.x + threadIdx.x;
    if (i >= n8) return;
    int4 v0 = in[2 * i];
    int4 v1 = in[2 * i + 1];
    uint4 o;
    o.x = pack_bf2((float)(v0.x + 66), (float)(v0.y + 66));
    o.y = pack_bf2((float)(v0.z + 66), (float)(v0.w + 66));
    o.z = pack_bf2((float)(v1.x + 66), (float)(v1.y + 66));
    o.w = pack_bf2((float)(v1.z + 66), (float)(v1.w + 66));
    out[i] = o;
}

// y int32 [K,N] -> bf16 yT [N,K] with (y-160). 64(K) x 32(N) tiles.
__global__ void convert_yT_kernel(const int* __restrict__ y,
                                  __nv_bfloat16* __restrict__ yT) {
    __shared__ __nv_bfloat16 tile[64][33];   // [k][n], padded
    int k0 = blockIdx.y * 64;
    int n0 = blockIdx.x * 32;
    int tx = threadIdx.x;   // 0..31
    int ty = threadIdx.y;   // 0..7

#pragma unroll
    for (int kk = ty; kk < 64; kk += 8) {
        int vv = y[(size_t)(k0 + kk) * NDIM + n0 + tx] - 160;
        tile[kk][tx] = __float2bfloat16_rn((float)vv);
    }
    __syncthreads();
#pragma unroll
    for (int nn = ty; nn < 32; nn += 8) {
        __nv_bfloat162 p;
        p.x = tile[2 * tx + 0][nn];
        p.y = tile[2 * tx + 1][nn];
        *(__nv_bfloat162*)(&yT[(size_t)(n0 + nn) * KDIM + k0 + 2 * tx]) = p;
    }
}

// ============================================================================
// GEMM tile body. 8 warps = 2(m) x 4(n); warp tile 64 x (16*TNN).
// TNN=4: CTA 128x256 (acc 128 regs). TNN=2: CTA 128x128 (tail).
// mma.m16n8k16.bf16, 4-stage cp.async ring, XOR-swizzled smem,
// bulk per-k16-step register double-buffered fragments.
// ============================================================================
template <int TNN>
DEVINL void gemm_tile(float* __restrict__ out, uint32_t sb, int tid,
                      int m0, int n0) {
    const char* A = (const char*)g_xb;
    const char* B = (const char*)g_yb;

    constexpr int TN = 64 * TNN;                  // 256 / 128
    constexpr int B_STG = TN * 128;               // 32 KB / 16 KB
    constexpr int STG_BYTES = A_STG + B_STG;      // 48 KB / 32 KB

    const int lane = tid & 31;
    const int wid = tid >> 5;      // 0..7
    const int wm = wid & 1;        // m: 0..1
    const int wn = wid >> 1;       // n: 0..3

    const int frag_row = ((lane >> 3) & 1) * 8 + (lane & 7);
    const int frag_kh = lane >> 4;

    const int rowA0 = wm * 64 + frag_row;           // + tm*16, tm<4
    const int rowB0 = wn * (TNN * 16) + frag_row;   // + gg*16, gg<TNN

    float acc[TNN * 32];
#pragma unroll
    for (int i = 0; i < TNN * 32; ++i) acc[i] = 0.0f;

    auto stage_copy = [&](int slot, int kt) {
        uint32_t abase = sb + slot * STG_BYTES;
        uint32_t bbase = abase + A_STG;
#pragma unroll
        for (int i = 0; i < 4; ++i) {               // A: 1024 chunks / 256 thr
            int idx = tid + i * NTHREADS;
            int row = idx >> 3, c = idx & 7;
            cp_async16(abase + row * 128 + ((c ^ (row & 7)) << 4),
                       A + (size_t)(m0 + row) * (KDIM * 2) + kt * 128 + c * 16);
        }
#pragma unroll
        for (int i = 0; i < 2 * TNN; ++i) {         // B: TN*8 chunks / 256 thr
            int idx = tid + i * NTHREADS;
            int row = idx >> 3, c = idx & 7;
            cp_async16(bbase + row * 128 + ((c ^ (row & 7)) << 4),
                       B + (size_t)(n0 + row) * (KDIM * 2) + kt * 128 + c * 16);
        }
    };

    auto load_A = [&](uint32_t abase, int ks, uint32_t afr[4][4]) {
#pragma unroll
        for (int tm = 0; tm < 4; ++tm) {
            int rowa = rowA0 + tm * 16;
            ldsm4(afr[tm],
                  abase + rowa * 128 + (((ks * 2 + frag_kh) ^ (rowa & 7)) << 4));
        }
    };
    auto load_B = [&](uint32_t bbase, int ks, uint32_t bfr[2 * TNN][2]) {
#pragma unroll
        for (int gg = 0; gg < TNN; ++gg) {
            uint32_t t4[4];
            int rowb = rowB0 + gg * 16;
            ldsm4(t4,
                  bbase + rowb * 128 + (((ks * 2 + frag_kh) ^ (rowb & 7)) << 4));
            bfr[2 * gg][0] = t4[0]; bfr[2 * gg][1] = t4[2];
            bfr[2 * gg + 1][0] = t4[1]; bfr[2 * gg + 1][1] = t4[3];
        }
    };

    // prologue
#pragma unroll
    for (int s = 0; s < STAGES - 1; ++s) {
        stage_copy(s, s);
        cp_commit();
    }
    cp_wait<STAGES - 2>();
    __syncthreads();

    uint32_t afr[2][4][4];
    uint32_t bfr[2][2 * TNN][2];
    int cur = 0;
    load_A(sb, 0, afr[0]);
    load_B(sb + A_STG, 0, bfr[0]);

    for (int kt = 0; kt < NK; ++kt) {
        int pf = kt + STAGES - 1;
        if (pf < NK) stage_copy(pf & 3, pf);
        cp_commit();

        uint32_t abase = sb + (kt & 3) * STG_BYTES;
        uint32_t bbase = abase + A_STG;
        uint32_t abase_n = sb + ((kt + 1) & 3) * STG_BYTES;
        uint32_t bbase_n = abase_n + A_STG;

#pragma unroll
        for (int ks = 0; ks < 4; ++ks) {
            int nxt = cur ^ 1;
            if (ks < 3) {
                // prefetch (kt, ks+1) while mma on (kt, ks)
                load_A(abase, ks + 1, afr[nxt]);
                load_B(bbase, ks + 1, bfr[nxt]);
            } else {
                // stage kt+1 becomes resident; prefetch its ks0
                cp_wait<STAGES - 2>();
                __syncthreads();
                load_A(abase_n, 0, afr[nxt]);
                load_B(bbase_n, 0, bfr[nxt]);
            }
#pragma unroll
            for (int tm = 0; tm < 4; ++tm)
#pragma unroll
                for (int tn = 0; tn < 2 * TNN; ++tn)
                    mma_bf16(&acc[(tm * 2 * TNN + tn) * 4],
                             afr[cur][tm], bfr[cur][tn]);
            cur = nxt;
        }
    }

    // epilogue: scale + store
    const int gq = lane >> 2;
    const int tig = lane & 3;
#pragma unroll
    for (int tm = 0; tm < 4; ++tm) {
        int m_top = m0 + wm * 64 + tm * 16 + gq;
        float* row0 = out + (size_t)m_top * NDIM;
        float* row1 = out + (size_t)(m_top + 8) * NDIM;
#pragma unroll
        for (int tn = 0; tn < 2 * TNN; ++tn) {
            int n = n0 + wn * (TNN * 16) + tn * 8 + tig * 2;
            const float* c = &acc[(tm * 2 * TNN + tn) * 4];
            float2 v0, v1;
            v0.x = c[0] * OUT_SCALE;
            v0.y = c[1] * OUT_SCALE;
            v1.x = c[2] * OUT_SCALE;
            v1.y = c[3] * OUT_SCALE;
            *(float2*)(row0 + n) = v0;
            *(float2*)(row1 + n) = v1;
        }
    }
}

// Rasterization over the 512 logical 128x256 tiles: groups of 8 m-tiles,
// n fast within group.
DEVINL void tile_coords(int t, int& m0, int& n0) {
    int g = t >> 7;
    int r = t & 127;
    m0 = (g * 8 + (r & 7)) * 128;
    n0 = (r >> 3) * 256;
}

__global__ void __launch_bounds__(NTHREADS, 1)
gemm_kernel(float* __restrict__ out, int nbig) {
    extern __shared__ __align__(1024) char smem[];
    const uint32_t sb = smem_u32(smem);
    const int tid = threadIdx.x;
    const int pid = blockIdx.x;

    if (pid < nbig) {
        int m0, n0;
        tile_coords(pid, m0, n0);
        gemm_tile<4>(out, sb, tid, m0, n0);
    } else {
        int s = pid - nbig;
        int m0, n0;
        tile_coords(nbig + (s >> 1), m0, n0);
        n0 += (s & 1) * 128;
        gemm_tile<2>(out, sb, tid, m0, n0);
    }
}

// ============================================================================
// Host
// ============================================================================
extern "C" void kernel_launch(void* const* d_in, const int* in_sizes, int n_in,
                              void* d_out, int out_size) {
    const int* x = (const int*)d_in[0];   // [M,K] int32
    const int* y = (const int*)d_in[1];   // [K,N] int32
    float* out = (float*)d_out;

    void *pxb = nullptr, *pyb = nullptr;
    cudaGetSymbolAddress(&pxb, g_xb);
    cudaGetSymbolAddress(&pyb, g_yb);

    int n8 = MDIM * KDIM / 8;
    convert_x_kernel<<<(n8 + 255) / 256, 256>>>((const int4*)x, (uint4*)pxb, n8);
    convert_yT_kernel<<<dim3(NDIM / 32, KDIM / 64), dim3(32, 8)>>>(
        y, (__nv_bfloat16*)pyb);

    static int sms = 0;
    static bool attr_set = false;
    if (!attr_set) {
        cudaFuncSetAttribute(gemm_kernel,
                             cudaFuncAttributeMaxDynamicSharedMemorySize,
                             SMEM_TOTAL);
        int dev = 0;
        cudaGetDevice(&dev);
        cudaDeviceGetAttribute(&sms, cudaDevAttrMultiProcessorCount, dev);
        if (sms <= 0) sms = 148;
        attr_set = true;
    }

    int w = NTILE / sms;                 // full big-tile waves
    int nbig = w * sms;
    if (nbig > NTILE) nbig = NTILE;
    int rem = NTILE - nbig;              // big-tile footprints left
    int grid = nbig + 2 * rem;           // each footprint -> two 128x128 CTAs

    gemm_kernel<<<grid, NTHREADS, SMEM_TOTAL>>>(out, nbig);
}

// round 15
// speedup vs baseline: 1.5108x; 1.0642x over previous
#include <cuda_runtime.h>
#include <cuda.h>
#include <cuda_bf16.h>
#include <cstdint>
#include <cstddef>
#include <cstring>

// ============================================================================
// out[M,N] = ((x + 66)*0.03) @ ((y - 160)*0.025)
// (x+66), (y-160) are exact integers in bf16 -> bf16 HMMA GEMM (fp32 acc),
// scale 7.5e-4 in epilogue.
// R15: GEMM identical to R11/R14 (proven best: 338.4us). Re-applying the
// fused conversion kernel (R13): x-convert and yT-transpose in disjoint grid
// halves so both DRAM streams run concurrently. R13's 480us was shown (clock
// back-calculation from ncu tensor-busy) to be DVFS throttling, not code;
// R14 confirmed recovery. This cleanly re-tests the fusion.
// ============================================================================

static constexpr int MDIM = 4096, NDIM = 4096, KDIM = 4096;

static constexpr int TM = 128;        // CTA M tile
static constexpr int TKE = 64;        // K elems (bf16) per stage = 128 B rows
static constexpr int NK = KDIM / TKE; // 64 mainloop iters
static constexpr int STAGES = 4;
static constexpr int NTHREADS = 256;  // 8 warps: 2 (m) x 4 (n)
static constexpr int A_STG = TM * 128;              // 16 KB
static constexpr int SMEM_TOTAL = STAGES * (A_STG + 256 * 128);  // 192 KB

static constexpr int NTILE = (MDIM / 128) * (NDIM / 256);   // 512 logical tiles

static constexpr float OUT_SCALE = 0.03f * 0.025f;   // 7.5e-4

// Scratch operands (device globals: no runtime allocation allowed)
__device__ __nv_bfloat16 g_xb[(size_t)MDIM * KDIM];   // A [M,K]: bf16(x+66)
__device__ __nv_bfloat16 g_yb[(size_t)NDIM * KDIM];   // Bt [N,K]: bf16(y-160)

#define DEVINL __device__ __forceinline__

DEVINL uint32_t smem_u32(const void* p) {
    uint32_t a;
    asm("{ .reg .u64 t; cvta.to.shared.u64 t, %1; cvt.u32.u64 %0, t; }"
        : "=r"(a) : "l"(p));
    return a;
}

DEVINL void cp_async16(uint32_t dst, const void* src) {
    asm volatile("cp.async.cg.shared.global [%0], [%1], 16;"
                 :: "r"(dst), "l"(src) : "memory");
}
DEVINL void cp_commit() { asm volatile("cp.async.commit_group;" ::: "memory"); }
template <int N>
DEVINL void cp_wait() { asm volatile("cp.async.wait_group %0;" :: "n"(N) : "memory"); }

DEVINL void ldsm4(uint32_t* r, uint32_t addr) {
    asm volatile("ldmatrix.sync.aligned.m8n8.x4.shared.b16 {%0,%1,%2,%3}, [%4];"
                 : "=r"(r[0]), "=r"(r[1]), "=r"(r[2]), "=r"(r[3]) : "r"(addr));
}

// m16n8k16 bf16 HMMA, f32 accumulate
DEVINL void mma_bf16(float* c, const uint32_t* a, const uint32_t* b) {
    asm volatile(
        "mma.sync.aligned.m16n8k16.row.col.f32.bf16.bf16.f32 "
        "{%0,%1,%2,%3}, {%4,%5,%6,%7}, {%8,%9}, {%0,%1,%2,%3};"
        : "+f"(c[0]), "+f"(c[1]), "+f"(c[2]), "+f"(c[3])
        : "r"(a[0]), "r"(a[1]), "r"(a[2]), "r"(a[3]), "r"(b[0]), "r"(b[1]));
}

// ============================================================================
// Fused conversion kernel (exact: shifted values are integers, |v| <= 256).
// Blocks [0, XBLKS): x int32 [M,K] -> bf16 (x+66), 32B load / 16B store.
// Blocks [XBLKS, XBLKS+YBLKS): y int32 [K,N] -> bf16 yT [N,K] (y-160),
// 64(K) x 32(N) transpose tiles via padded smem. Both halves stream DRAM
// concurrently.
// ============================================================================
static constexpr int XBLKS = (MDIM * KDIM / 8) / 256;            // 8192
static constexpr int YBLKS = (NDIM / 32) * (KDIM / 64);          // 8192

DEVINL uint32_t pack_bf2(float a, float b) {
    __nv_bfloat162 p = __floats2bfloat162_rn(a, b);
    uint32_t u;
    memcpy(&u, &p, 4);
    return u;
}

__global__ void __launch_bounds__(256)
convert_fused_kernel(const int4* __restrict__ x4, const int* __restrict__ y,
                     uint4* __restrict__ xb4, __nv_bfloat16* __restrict__ yT) {
    __shared__ __nv_bfloat16 tile[64][33];   // [k][n], padded (yT half only)
    int bid = blockIdx.x;
    int tid = threadIdx.x;

    if (bid < XBLKS) {
        // ---- x half: 8 int32 -> 8 bf16 per thread ----
        int i = bid * 256 + tid;
        int4 v0 = x4[2 * i];
        int4 v1 = x4[2 * i + 1];
        uint4 o;
        o.x = pack_bf2((float)(v0.x + 66), (float)(v0.y + 66));
        o.y = pack_bf2((float)(v0.z + 66), (float)(v0.w + 66));
        o.z = pack_bf2((float)(v1.x + 66), (float)(v1.y + 66));
        o.w = pack_bf2((float)(v1.z + 66), (float)(v1.w + 66));
        xb4[i] = o;
    } else {
        // ---- yT half: 64(K) x 32(N) transpose tile ----
        int b = bid - XBLKS;
        int n0 = (b & 127) * 32;          // 128 n-tiles
        int k0 = (b >> 7) * 64;           // 64 k-tiles
        int tx = tid & 31;                // 0..31 (n)
        int ty = tid >> 5;                // 0..7

#pragma unroll
        for (int kk = ty; kk < 64; kk += 8) {
            int vv = y[(size_t)(k0 + kk) * NDIM + n0 + tx] - 160;
            tile[kk][tx] = __float2bfloat16_rn((float)vv);
        }
        __syncthreads();
#pragma unroll
        for (int nn = ty; nn < 32; nn += 8) {
            __nv_bfloat162 p;
            p.x = tile[2 * tx + 0][nn];
            p.y = tile[2 * tx + 1][nn];
            *(__nv_bfloat162*)(&yT[(size_t)(n0 + nn) * KDIM + k0 + 2 * tx]) = p;
        }
    }
}

// ============================================================================
// GEMM tile body (R11, unchanged). 8 warps = 2(m) x 4(n); warp tile
// 64 x (16*TNN). TNN=4: CTA 128x256. TNN=2: CTA 128x128 (tail).
// mma.m16n8k16.bf16, 4-stage cp.async ring, XOR-swizzled smem,
// bulk per-k16-step register double-buffered fragments.
// ============================================================================
template <int TNN>
DEVINL void gemm_tile(float* __restrict__ out, uint32_t sb, int tid,
                      int m0, int n0) {
    const char* A = (const char*)g_xb;
    const char* B = (const char*)g_yb;

    constexpr int TN = 64 * TNN;                  // 256 / 128
    constexpr int B_STG = TN * 128;               // 32 KB / 16 KB
    constexpr int STG_BYTES = A_STG + B_STG;      // 48 KB / 32 KB

    const int lane = tid & 31;
    const int wid = tid >> 5;      // 0..7
    const int wm = wid & 1;        // m: 0..1
    const int wn = wid >> 1;       // n: 0..3

    const int frag_row = ((lane >> 3) & 1) * 8 + (lane & 7);
    const int frag_kh = lane >> 4;

    const int rowA0 = wm * 64 + frag_row;           // + tm*16, tm<4
    const int rowB0 = wn * (TNN * 16) + frag_row;   // + gg*16, gg<TNN

    float acc[TNN * 32];
#pragma unroll
    for (int i = 0; i < TNN * 32; ++i) acc[i] = 0.0f;

    auto stage_copy = [&](int slot, int kt) {
        uint32_t abase = sb + slot * STG_BYTES;
        uint32_t bbase = abase + A_STG;
#pragma unroll
        for (int i = 0; i < 4; ++i) {               // A: 1024 chunks / 256 thr
            int idx = tid + i * NTHREADS;
            int row = idx >> 3, c = idx & 7;
            cp_async16(abase + row * 128 + ((c ^ (row & 7)) << 4),
                       A + (size_t)(m0 + row) * (KDIM * 2) + kt * 128 + c * 16);
        }
#pragma unroll
        for (int i = 0; i < 2 * TNN; ++i) {         // B: TN*8 chunks / 256 thr
            int idx = tid + i * NTHREADS;
            int row = idx >> 3, c = idx & 7;
            cp_async16(bbase + row * 128 + ((c ^ (row & 7)) << 4),
                       B + (size_t)(n0 + row) * (KDIM * 2) + kt * 128 + c * 16);
        }
    };

    auto load_A = [&](uint32_t abase, int ks, uint32_t afr[4][4]) {
#pragma unroll
        for (int tm = 0; tm < 4; ++tm) {
            int rowa = rowA0 + tm * 16;
            ldsm4(afr[tm],
                  abase + rowa * 128 + (((ks * 2 + frag_kh) ^ (rowa & 7)) << 4));
        }
    };
    auto load_B = [&](uint32_t bbase, int ks, uint32_t bfr[2 * TNN][2]) {
#pragma unroll
        for (int gg = 0; gg < TNN; ++gg) {
            uint32_t t4[4];
            int rowb = rowB0 + gg * 16;
            ldsm4(t4,
                  bbase + rowb * 128 + (((ks * 2 + frag_kh) ^ (rowb & 7)) << 4));
            bfr[2 * gg][0] = t4[0]; bfr[2 * gg][1] = t4[2];
            bfr[2 * gg + 1][0] = t4[1]; bfr[2 * gg + 1][1] = t4[3];
        }
    };

    // prologue
#pragma unroll
    for (int s = 0; s < STAGES - 1; ++s) {
        stage_copy(s, s);
        cp_commit();
    }
    cp_wait<STAGES - 2>();
    __syncthreads();

    uint32_t afr[2][4][4];
    uint32_t bfr[2][2 * TNN][2];
    int cur = 0;
    load_A(sb, 0, afr[0]);
    load_B(sb + A_STG, 0, bfr[0]);

    for (int kt = 0; kt < NK; ++kt) {
        int pf = kt + STAGES - 1;
        if (pf < NK) stage_copy(pf & 3, pf);
        cp_commit();

        uint32_t abase = sb + (kt & 3) * STG_BYTES;
        uint32_t bbase = abase + A_STG;
        uint32_t abase_n = sb + ((kt + 1) & 3) * STG_BYTES;
        uint32_t bbase_n = abase_n + A_STG;

#pragma unroll
        for (int ks = 0; ks < 4; ++ks) {
            int nxt = cur ^ 1;
            if (ks < 3) {
                // prefetch (kt, ks+1) while mma on (kt, ks)
                load_A(abase, ks + 1, afr[nxt]);
                load_B(bbase, ks + 1, bfr[nxt]);
            } else {
                // stage kt+1 becomes resident; prefetch its ks0
                cp_wait<STAGES - 2>();
                __syncthreads();
                load_A(abase_n, 0, afr[nxt]);
                load_B(bbase_n, 0, bfr[nxt]);
            }
#pragma unroll
            for (int tm = 0; tm < 4; ++tm)
#pragma unroll
                for (int tn = 0; tn < 2 * TNN; ++tn)
                    mma_bf16(&acc[(tm * 2 * TNN + tn) * 4],
                             afr[cur][tm], bfr[cur][tn]);
            cur = nxt;
        }
    }

    // epilogue: scale + store
    const int gq = lane >> 2;
    const int tig = lane & 3;
#pragma unroll
    for (int tm = 0; tm < 4; ++tm) {
        int m_top = m0 + wm * 64 + tm * 16 + gq;
        float* row0 = out + (size_t)m_top * NDIM;
        float* row1 = out + (size_t)(m_top + 8) * NDIM;
#pragma unroll
        for (int tn = 0; tn < 2 * TNN; ++tn) {
            int n = n0 + wn * (TNN * 16) + tn * 8 + tig * 2;
            const float* c = &acc[(tm * 2 * TNN + tn) * 4];
            float2 v0, v1;
            v0.x = c[0] * OUT_SCALE;
            v0.y = c[1] * OUT_SCALE;
            v1.x = c[2] * OUT_SCALE;
            v1.y = c[3] * OUT_SCALE;
            *(float2*)(row0 + n) = v0;
            *(float2*)(row1 + n) = v1;
        }
    }
}

// Rasterization over the 512 logical 128x256 tiles: groups of 8 m-tiles,
// n fast within group.
DEVINL void tile_coords(int t, int& m0, int& n0) {
    int g = t >> 7;
    int r = t & 127;
    m0 = (g * 8 + (r & 7)) * 128;
    n0 = (r >> 3) * 256;
}

__global__ void __launch_bounds__(NTHREADS, 1)
gemm_kernel(float* __restrict__ out, int nbig) {
    extern __shared__ __align__(1024) char smem[];
    const uint32_t sb = smem_u32(smem);
    const int tid = threadIdx.x;
    const int pid = blockIdx.x;

    if (pid < nbig) {
        int m0, n0;
        tile_coords(pid, m0, n0);
        gemm_tile<4>(out, sb, tid, m0, n0);
    } else {
        int s = pid - nbig;
        int m0, n0;
        tile_coords(nbig + (s >> 1), m0, n0);
        n0 += (s & 1) * 128;
        gemm_tile<2>(out, sb, tid, m0, n0);
    }
}

// ============================================================================
// Host
// ============================================================================
extern "C" void kernel_launch(void* const* d_in, const int* in_sizes, int n_in,
                              void* d_out, int out_size) {
    const int* x = (const int*)d_in[0];   // [M,K] int32
    const int* y = (const int*)d_in[1];   // [K,N] int32
    float* out = (float*)d_out;

    void *pxb = nullptr, *pyb = nullptr;
    cudaGetSymbolAddress(&pxb, g_xb);
    cudaGetSymbolAddress(&pyb, g_yb);

    // 1) fused conversions: x and yT halves stream DRAM concurrently
    convert_fused_kernel<<<XBLKS + YBLKS, 256>>>(
        (const int4*)x, y, (uint4*)pxb, (__nv_bfloat16*)pyb);

    // 2) GEMM
    static int sms = 0;
    static bool attr_set = false;
    if (!attr_set) {
        cudaFuncSetAttribute(gemm_kernel,
                             cudaFuncAttributeMaxDynamicSharedMemorySize,
                             SMEM_TOTAL);
        int dev = 0;
        cudaGetDevice(&dev);
        cudaDeviceGetAttribute(&sms, cudaDevAttrMultiProcessorCount, dev);
        if (sms <= 0) sms = 148;
        attr_set = true;
    }

    int w = NTILE / sms;                 // full big-tile waves
    int nbig = w * sms;
    if (nbig > NTILE) nbig = NTILE;
    int rem = NTILE - nbig;              // big-tile footprints left
    int grid = nbig + 2 * rem;           // each footprint -> two 128x128 CTAs

    gemm_kernel<<<grid, NTHREADS, SMEM_TOTAL>>>(out, nbig);
}